// round 15
// baseline (speedup 1.0000x reference)
#include <cuda_runtime.h>
#include <cuda_bf16.h>
#include <cstdint>

#define Bv   16
#define Nv   5000
#define Ev   160000
#define BNv  80000
#define BEv  2560000
#define ETOTv 2640000
#define OUT_MAIN 5120000   // BNv * 64
#define NPART 625          // Ev / 256
#define CAP  128           // bucket capacity per destination
#define HEADBLKS 40        // 128-row blocks covered by head (head = rows 0..5119)

// ---------------- scratch (static __device__, no allocs) ----------------
__device__ float  g_xlS[Nv * 64];
__device__ float  g_aS[Nv];
__device__ float  g_aD[Nv];
__device__ int    g_bcnt[Nv + 2];     // [Nv] reused as float sum(ea)
__device__ float2 g_bsv[Nv * CAP];    // packed (src-as-float-bits, ea)
__device__ int    g_bedge[Nv * CAP];
__device__ float  g_alphaC[Nv * CAP]; // unnormalized p, CSR-slot order
__device__ float  g_alphaP[Ev];       // normalized alpha per unique edge
__device__ float  g_selfNorm[Nv];

// ---------------- helpers ----------------
__device__ __forceinline__ uint32_t smem_to_u32(const void* p) {
    uint32_t a;
    asm("{ .reg .u64 t; cvta.to.shared.u64 t, %1; cvt.u32.u64 %0, t; }" : "=r"(a) : "l"(p));
    return a;
}
__device__ __forceinline__ uint32_t pack_hi(float2 v) {
    __nv_bfloat162 h = __float22bfloat162_rn(v);
    return *(uint32_t*)&h;
}
__device__ __forceinline__ uint32_t pack_lo(float2 v, uint32_t hi) {
    __nv_bfloat162 h = *(__nv_bfloat162*)&hi;
    float2 hf = __bfloat1622float2(h);
    float2 r; r.x = v.x - hf.x; r.y = v.y - hf.y;
    __nv_bfloat162 l = __float22bfloat162_rn(r);
    return *(uint32_t*)&l;
}
#define LDMX2(r, a) \
    asm volatile("ldmatrix.sync.aligned.m8n8.x2.shared.b16 {%0,%1}, [%2];" \
        : "=r"((r)[0]), "=r"((r)[1]) : "r"(a))
#define MMA16816(c, a, b) \
    asm volatile("mma.sync.aligned.m16n8k16.row.col.f32.bf16.bf16.f32 " \
        "{%0,%1,%2,%3}, {%4,%5,%6,%7}, {%8,%9}, {%0,%1,%2,%3};" \
        : "+f"((c)[0]), "+f"((c)[1]), "+f"((c)[2]), "+f"((c)[3]) \
        : "r"((a)[0]), "r"((a)[1]), "r"((a)[2]), "r"((a)[3]), "r"((b)[0]), "r"((b)[1]))

// stage W -> smem bf16 hi|lo image [64 n-rows][72 bf16] (inline conversion)
__device__ __forceinline__ void stage_B(char* smB, const float* __restrict__ W, int tid) {
#pragma unroll
    for (int it = 0; it < 8; it++) {
        int i = tid + it * 256;
        int c = i >> 5, cp = i & 31;
        float2 wv = *(const float2*)(W + c * 64 + cp * 2);
        uint32_t hu = pack_hi(wv);
        uint32_t lu = pack_lo(wv, hu);
        *(uint32_t*)(smB + c * 144 + cp * 4) = hu;
        *(uint32_t*)(smB + 9216 + c * 144 + cp * 4) = lu;
    }
}

// ---- REST gemm: M=128 tile (rows 5120..79999), no attn epilogue needed ----
__global__ void __launch_bounds__(256, 2) k_gemm128(const float* __restrict__ x,
                                                    const float* __restrict__ W,
                                                    const float* __restrict__ bias,
                                                    float* __restrict__ out,
                                                    int blockOff) {
    __shared__ char smB[18432];
    int tid = threadIdx.x, wid = tid >> 5, lane = tid & 31;
    int nb = (blockIdx.x + blockOff) * 128;

    stage_B(smB, W, tid);

    int r0 = wid * 16 + (lane >> 2);
    const float* xr = x + (size_t)(nb + r0) * 64 + (lane & 3) * 2;
    float2 v[4][4];
#pragma unroll
    for (int kc = 0; kc < 4; kc++) {
        v[kc][0] = *(const float2*)(xr + kc * 16);
        v[kc][1] = *(const float2*)(xr + 8 * 64 + kc * 16);
        v[kc][2] = *(const float2*)(xr + kc * 16 + 8);
        v[kc][3] = *(const float2*)(xr + 8 * 64 + kc * 16 + 8);
    }
    uint32_t ahi[4][4], alo[4][4];
#pragma unroll
    for (int kc = 0; kc < 4; kc++)
#pragma unroll
        for (int j = 0; j < 4; j++) {
            ahi[kc][j] = pack_hi(v[kc][j]);
            alo[kc][j] = pack_lo(v[kc][j], ahi[kc][j]);
        }
    __syncthreads();

    uint32_t sb = smem_to_u32(smB);
    uint32_t bOff = (lane & 7) * 144 + ((lane >> 3) & 1) * 16;

    float acc[8][4];
#pragma unroll
    for (int nt = 0; nt < 8; nt++)
#pragma unroll
        for (int j = 0; j < 4; j++) acc[nt][j] = 0.f;

#pragma unroll
    for (int kc = 0; kc < 4; kc++) {
        uint32_t bh[8][2], bl[8][2];
#pragma unroll
        for (int nt = 0; nt < 8; nt++) {
            uint32_t ba = sb + nt * 1152 + bOff + kc * 32;
            LDMX2(bh[nt], ba);
            LDMX2(bl[nt], ba + 9216);
        }
#pragma unroll
        for (int nt = 0; nt < 8; nt++) {
            MMA16816(acc[nt], ahi[kc], bh[nt]);
            MMA16816(acc[nt], ahi[kc], bl[nt]);
            MMA16816(acc[nt], alo[kc], bh[nt]);
        }
    }

    int n0 = nb + r0, n1 = n0 + 8;
#pragma unroll
    for (int nt = 0; nt < 8; nt++) {
        int col = nt * 8 + (lane & 3) * 2;
        float2 bb2 = *(const float2*)(bias + col);
        float2 o0, o1;
        o0.x = acc[nt][0] + bb2.x; o0.y = acc[nt][1] + bb2.y;
        o1.x = acc[nt][2] + bb2.x; o1.y = acc[nt][3] + bb2.y;
        *(float2*)(out + (size_t)n0 * 64 + col) = o0;
        *(float2*)(out + (size_t)n1 * 64 + col) = o1;
    }
}

// ---- HEAD gemm: M=64 tile (rows 0..5119), xl + attn-dot epilogue ----
__global__ void __launch_bounds__(256, 2) k_gemm64(const float* __restrict__ x,
                                                   const float* __restrict__ W,
                                                   const float* __restrict__ bias,
                                                   const float* __restrict__ attS,
                                                   const float* __restrict__ attD,
                                                   float* __restrict__ out) {
    __shared__ char smB[18432];
    __shared__ float PS[64], PD[64];
    int tid = threadIdx.x, wid = tid >> 5, lane = tid & 31;
    int nb = blockIdx.x * 64;

    stage_B(smB, W, tid);

    int rg = (wid & 3) * 16;          // row group within 64-row tile
    int cg = (wid >> 2) * 32;         // column half: 0 or 32
    int rloc = rg + (lane >> 2);
    int r0 = nb + rloc;
    const float* xr = x + (size_t)r0 * 64 + (lane & 3) * 2;
    float2 v[4][4];
#pragma unroll
    for (int kc = 0; kc < 4; kc++) {
        v[kc][0] = *(const float2*)(xr + kc * 16);
        v[kc][1] = *(const float2*)(xr + 8 * 64 + kc * 16);
        v[kc][2] = *(const float2*)(xr + kc * 16 + 8);
        v[kc][3] = *(const float2*)(xr + 8 * 64 + kc * 16 + 8);
    }
    uint32_t ahi[4][4], alo[4][4];
#pragma unroll
    for (int kc = 0; kc < 4; kc++)
#pragma unroll
        for (int j = 0; j < 4; j++) {
            ahi[kc][j] = pack_hi(v[kc][j]);
            alo[kc][j] = pack_lo(v[kc][j], ahi[kc][j]);
        }
    __syncthreads();

    uint32_t sb = smem_to_u32(smB);
    uint32_t bOff = (lane & 7) * 144 + ((lane >> 3) & 1) * 16;
    int ntBase = cg >> 3;             // 0 or 4

    float acc[4][4];
#pragma unroll
    for (int nt = 0; nt < 4; nt++)
#pragma unroll
        for (int j = 0; j < 4; j++) acc[nt][j] = 0.f;

#pragma unroll
    for (int kc = 0; kc < 4; kc++) {
        uint32_t bh[4][2], bl[4][2];
#pragma unroll
        for (int nt = 0; nt < 4; nt++) {
            uint32_t ba = sb + (ntBase + nt) * 1152 + bOff + kc * 32;
            LDMX2(bh[nt], ba);
            LDMX2(bl[nt], ba + 9216);
        }
#pragma unroll
        for (int nt = 0; nt < 4; nt++) {
            MMA16816(acc[nt], ahi[kc], bh[nt]);
            MMA16816(acc[nt], ahi[kc], bl[nt]);
            MMA16816(acc[nt], alo[kc], bh[nt]);
        }
    }

    int n0 = nb + rloc, n1 = n0 + 8;
#pragma unroll
    for (int nt = 0; nt < 4; nt++) {
        int col = cg + nt * 8 + (lane & 3) * 2;
        float2 bb2 = *(const float2*)(bias + col);
        float2 o0, o1;
        o0.x = acc[nt][0] + bb2.x; o0.y = acc[nt][1] + bb2.y;
        o1.x = acc[nt][2] + bb2.x; o1.y = acc[nt][3] + bb2.y;
        *(float2*)(out + (size_t)n0 * 64 + col) = o0;
        *(float2*)(out + (size_t)n1 * 64 + col) = o1;
        if (n0 < Nv) {
            float2 s0; s0.x = acc[nt][0]; s0.y = acc[nt][1];
            *(float2*)(g_xlS + n0 * 64 + col) = s0;
        }
        if (n1 < Nv) {
            float2 s1; s1.x = acc[nt][2]; s1.y = acc[nt][3];
            *(float2*)(g_xlS + n1 * 64 + col) = s1;
        }
    }
    // attn dots: partial over this warp's 32 cols, quad-reduce, cross-warp combine
    float ps0 = 0.f, pd0 = 0.f, ps1 = 0.f, pd1 = 0.f;
#pragma unroll
    for (int nt = 0; nt < 4; nt++) {
        int col = cg + nt * 8 + (lane & 3) * 2;
        float2 a2 = *(const float2*)(attS + col);
        float2 d2 = *(const float2*)(attD + col);
        ps0 += acc[nt][0] * a2.x + acc[nt][1] * a2.y;
        pd0 += acc[nt][0] * d2.x + acc[nt][1] * d2.y;
        ps1 += acc[nt][2] * a2.x + acc[nt][3] * a2.y;
        pd1 += acc[nt][2] * d2.x + acc[nt][3] * d2.y;
    }
#pragma unroll
    for (int o = 1; o <= 2; o <<= 1) {
        ps0 += __shfl_xor_sync(0xffffffffu, ps0, o);
        pd0 += __shfl_xor_sync(0xffffffffu, pd0, o);
        ps1 += __shfl_xor_sync(0xffffffffu, ps1, o);
        pd1 += __shfl_xor_sync(0xffffffffu, pd1, o);
    }
    if (cg == 32 && (lane & 3) == 0) {
        PS[rloc] = ps0; PD[rloc] = pd0;
        PS[rloc + 8] = ps1; PD[rloc + 8] = pd1;
    }
    __syncthreads();
    if (cg == 0 && (lane & 3) == 0) {
        if (n0 < Nv) { g_aS[n0] = ps0 + PS[rloc];     g_aD[n0] = pd0 + PD[rloc]; }
        if (n1 < Nv) { g_aS[n1] = ps1 + PS[rloc + 8]; g_aD[n1] = pd1 + PD[rloc + 8]; }
    }
}

// ------- bucket scatter + ea sum (packed payload) -------
__global__ void k_scatter(const int* __restrict__ ei, const float* __restrict__ ea) {
    int e = blockIdx.x * 256 + threadIdx.x;
    int d = ei[Ev + e];
    int s = ei[e];
    float v = ea[e];
    int pos = atomicAdd(&g_bcnt[d], 1);
    int idx = d * CAP + pos;
    float2 sv; sv.x = __int_as_float(s); sv.y = v;
    g_bsv[idx] = sv;
    g_bedge[idx] = e;
    float t = v;
#pragma unroll
    for (int o = 16; o; o >>= 1) t += __shfl_xor_sync(0xffffffffu, t, o);
    __shared__ float sh[8];
    if ((threadIdx.x & 31) == 0) sh[threadIdx.x >> 5] = t;
    __syncthreads();
    if (threadIdx.x < 8) {
        float w = sh[threadIdx.x];
#pragma unroll
        for (int o = 4; o; o >>= 1) w += __shfl_xor_sync(0xffu, w, o);
        if (threadIdx.x == 0) atomicAdd((float*)g_bcnt + Nv, w);
    }
}

// ------- per-destination softmax + aggregation: one warp per dst -------
__global__ void __launch_bounds__(256) k_dst(const float* __restrict__ W_edge,
                                             const float* __restrict__ attE,
                                             const float* __restrict__ bias,
                                             float* __restrict__ out) {
    int wIdx = threadIdx.x >> 5;
    int d = blockIdx.x * 8 + wIdx;
    int lane = threadIdx.x & 31;
    float cv = W_edge[lane] * attE[lane] + W_edge[lane + 32] * attE[lane + 32];
#pragma unroll
    for (int o = 16; o; o >>= 1) cv += __shfl_xor_sync(0xffffffffu, cv, o);
    float meanC = ((const float*)g_bcnt)[Nv] * (1.f / (float)Ev) * cv;

    int cnt = g_bcnt[d];
    int base = d * CAP;
    float aDd = g_aD[d];
    float pSelf;
    {
        float xv = g_aS[d] + aDd + meanC;
        xv = xv > 0.f ? xv : 0.2f * xv;
        pSelf = __expf(xv);
    }
    __shared__ float sP[8][32];
    __shared__ int   sS[8][32];
    float a0x = 0.f, a0y = 0.f, a1x = 0.f, a1y = 0.f;
    float a2x = 0.f, a2y = 0.f, a3x = 0.f, a3y = 0.f;
    float psum = 0.f;
    for (int b0 = 0; b0 < cnt; b0 += 32) {
        int m = cnt - b0; if (m > 32) m = 32;
        if (lane < m) {
            int idx = base + b0 + lane;
            float2 sv = g_bsv[idx];
            int s = __float_as_int(sv.x);
            float xv = g_aS[s] + aDd + sv.y * cv;
            xv = xv > 0.f ? xv : 0.2f * xv;
            float p = __expf(xv);
            psum += p;
            sP[wIdx][lane] = p;
            sS[wIdx][lane] = s;
            g_alphaC[idx] = p;
        }
        __syncwarp();
        int j = 0;
        for (; j + 4 <= m; j += 4) {
            float p0 = sP[wIdx][j],     p1 = sP[wIdx][j + 1];
            float p2 = sP[wIdx][j + 2], p3 = sP[wIdx][j + 3];
            int   q0 = sS[wIdx][j],     q1 = sS[wIdx][j + 1];
            int   q2 = sS[wIdx][j + 2], q3 = sS[wIdx][j + 3];
            float2 v0 = *(const float2*)(g_xlS + q0 * 64 + lane * 2);
            float2 v1 = *(const float2*)(g_xlS + q1 * 64 + lane * 2);
            float2 v2 = *(const float2*)(g_xlS + q2 * 64 + lane * 2);
            float2 v3 = *(const float2*)(g_xlS + q3 * 64 + lane * 2);
            a0x += p0 * v0.x; a0y += p0 * v0.y;
            a1x += p1 * v1.x; a1y += p1 * v1.y;
            a2x += p2 * v2.x; a2y += p2 * v2.y;
            a3x += p3 * v3.x; a3y += p3 * v3.y;
        }
        for (; j < m; j++) {
            float p0 = sP[wIdx][j];
            int   q0 = sS[wIdx][j];
            float2 v0 = *(const float2*)(g_xlS + q0 * 64 + lane * 2);
            a0x += p0 * v0.x; a0y += p0 * v0.y;
        }
        __syncwarp();
    }
    float accx = (a0x + a1x) + (a2x + a3x);
    float accy = (a0y + a1y) + (a2y + a3y);
#pragma unroll
    for (int o = 16; o; o >>= 1) psum += __shfl_xor_sync(0xffffffffu, psum, o);
    float denom = (float)Bv * psum + pSelf;
    float rd = 1.f / (denom + 1e-16f);
    float2 xs = *(const float2*)(g_xlS + d * 64 + lane * 2);
    float2 bb = *(const float2*)(bias + lane * 2);
    float2 o2;
    o2.x = ((float)Bv * accx + pSelf * xs.x) * rd + bb.x;
    o2.y = ((float)Bv * accy + pSelf * xs.y) * rd + bb.y;
    *(float2*)(out + (long long)d * 64 + lane * 2) = o2;
    if (lane == 0) g_selfNorm[d] = pSelf * rd;
    for (int i = lane; i < cnt; i += 32) {
        int idx = base + i;
        g_alphaP[g_bedge[idx]] = g_alphaC[idx] * rd;
    }
}

// ------- tail float4 generators -------
__device__ __forceinline__ float4 tail_sd_val(const int* __restrict__ ei, int i) {
    float4 v;
    if (i < ETOTv) {
        if (i < BEv) {
            int e = i - (i / Ev) * Ev;
            v.x = (float)ei[e]; v.y = (float)ei[e + 1];
            v.z = (float)ei[e + 2]; v.w = (float)ei[e + 3];
        } else {
            float b0 = (float)(i - BEv);
            v.x = b0; v.y = b0 + 1.f; v.z = b0 + 2.f; v.w = b0 + 3.f;
        }
    } else {
        int k = i - ETOTv;
        if (k < BEv) {
            int e = k - (k / Ev) * Ev;
            v.x = (float)ei[Ev + e]; v.y = (float)ei[Ev + e + 1];
            v.z = (float)ei[Ev + e + 2]; v.w = (float)ei[Ev + e + 3];
        } else {
            float b0 = (float)(k - BEv);
            v.x = b0; v.y = b0 + 1.f; v.z = b0 + 2.f; v.w = b0 + 3.f;
        }
    }
    return v;
}

__global__ void k_tail_sd(const int* __restrict__ ei, float* __restrict__ outTail) {
    int base4 = blockIdx.x * 1024 + threadIdx.x;
    float4 v[4];
    int idx[4];
#pragma unroll
    for (int k = 0; k < 4; k++) {
        idx[k] = base4 + k * 256;
        int i = idx[k] * 4;
        if (i < 2 * ETOTv) v[k] = tail_sd_val(ei, i);
    }
#pragma unroll
    for (int k = 0; k < 4; k++) {
        int i = idx[k] * 4;
        if (i < 2 * ETOTv) *(float4*)(outTail + i) = v[k];
    }
}

__device__ __forceinline__ float4 tail_alpha_val(int i) {
    float4 v;
    if (i < BEv) {
        int e = i - (i / Ev) * Ev;
        v = *(const float4*)(g_alphaP + e);
    } else {
        int d = i - BEv;
        if (d + 3 < Nv) {
            v.x = g_selfNorm[d]; v.y = g_selfNorm[d + 1];
            v.z = g_selfNorm[d + 2]; v.w = g_selfNorm[d + 3];
        } else {
            v.x = (d     < Nv) ? g_selfNorm[d]     : 1.0f;
            v.y = (d + 1 < Nv) ? g_selfNorm[d + 1] : 1.0f;
            v.z = (d + 2 < Nv) ? g_selfNorm[d + 2] : 1.0f;
            v.w = (d + 3 < Nv) ? g_selfNorm[d + 3] : 1.0f;
        }
    }
    return v;
}

__global__ void k_tail_alpha(float* __restrict__ outA, int totalA) {
    int base4 = blockIdx.x * 1024 + threadIdx.x;
    float4 v[4];
    int idx[4];
#pragma unroll
    for (int k = 0; k < 4; k++) {
        idx[k] = base4 + k * 256;
        int i = idx[k] * 4;
        if (i < totalA) v[k] = tail_alpha_val(i);
    }
#pragma unroll
    for (int k = 0; k < 4; k++) {
        int i = idx[k] * 4;
        if (i < totalA) *(float4*)(outA + i) = v[k];
    }
}

// ---------------- launch ----------------
extern "C" void kernel_launch(void* const* d_in, const int* in_sizes, int n_in,
                              void* d_out, int out_size) {
    const float* data   = (const float*)d_in[0];
    const int*   ei     = (const int*)  d_in[1];
    const float* ea     = (const float*)d_in[2];
    const float* W      = (const float*)d_in[3];
    const float* W_edge = (const float*)d_in[4];
    const float* attS   = (const float*)d_in[5];
    const float* attD   = (const float*)d_in[6];
    const float* attE   = (const float*)d_in[7];
    const float* bias   = (const float*)d_in[8];
    float* out = (float*)d_out;

    static cudaStream_t sB = nullptr, sC = nullptr, sD = nullptr;
    static cudaEvent_t eFork = nullptr, eB = nullptr, eC = nullptr, eD = nullptr;
    if (!sB) {
        int prLo = 0, prHi = 0;
        cudaDeviceGetStreamPriorityRange(&prLo, &prHi);
        cudaStreamCreateWithFlags(&sB, cudaStreamNonBlocking);
        cudaStreamCreateWithFlags(&sC, cudaStreamNonBlocking);
        cudaStreamCreateWithPriority(&sD, cudaStreamNonBlocking, prLo); // bulk gemm lowest prio
        cudaEventCreateWithFlags(&eFork, cudaEventDisableTiming);
        cudaEventCreateWithFlags(&eB, cudaEventDisableTiming);
        cudaEventCreateWithFlags(&eC, cudaEventDisableTiming);
        cudaEventCreateWithFlags(&eD, cudaEventDisableTiming);
    }

    void* bcntAddr = nullptr;
    cudaGetSymbolAddress(&bcntAddr, g_bcnt);

    cudaEventRecord(eFork, 0);
    cudaStreamWaitEvent(sB, eFork, 0);
    cudaStreamWaitEvent(sC, eFork, 0);
    cudaStreamWaitEvent(sD, eFork, 0);

    // HEAD gemm first on main (critical path), rest on low-prio sD
    k_gemm64<<<80, 256>>>(data, W, bias, attS, attD, out);
    k_gemm128<<<BNv / 128 - HEADBLKS, 256, 0, sD>>>(data, W, bias, out, HEADBLKS);
    cudaEventRecord(eD, sD);

    // side chain: bucket CSR build
    cudaMemsetAsync(bcntAddr, 0, (Nv + 2) * sizeof(int), sB);
    k_scatter<<<NPART, 256, 0, sB>>>(ei, ea);
    cudaEventRecord(eB, sB);

    // tail src/dst rows (independent)
    if (out_size > OUT_MAIN) {
        int nblk = (2 * ETOTv / 4 + 1023) / 1024;
        k_tail_sd<<<nblk, 256, 0, sC>>>(ei, out + OUT_MAIN);
    }
    cudaEventRecord(eC, sC);

    // main: wait CSR, then softmax/aggregate (overlaps gemm_rest), alpha tail
    cudaStreamWaitEvent(0, eB, 0);
    k_dst<<<Nv / 8, 256>>>(W_edge, attE, bias, out);

    if (out_size > OUT_MAIN) {
        int totalA = out_size - OUT_MAIN - 2 * ETOTv;
        if (totalA > 0) {
            int nblk = ((totalA + 3) / 4 + 1023) / 1024;
            k_tail_alpha<<<nblk, 256>>>(out + OUT_MAIN + 2 * ETOTv, totalA);
        }
    }

    cudaStreamWaitEvent(0, eC, 0);
    cudaStreamWaitEvent(0, eD, 0);
}

// round 16
// speedup vs baseline: 1.1117x; 1.1117x over previous
#include <cuda_runtime.h>
#include <cuda_bf16.h>
#include <cstdint>

#define Bv   16
#define Nv   5000
#define Ev   160000
#define BNv  80000
#define BEv  2560000
#define ETOTv 2640000
#define OUT_MAIN 5120000   // BNv * 64
#define NPART 625          // Ev / 256
#define CAP  128           // bucket capacity per destination
#define HEADBLKS 40        // 128-row blocks covered by head (rows 0..5119)

// ---------------- scratch (static __device__, no allocs) ----------------
// invariant: g_bcnt is all-zero at the start of every kernel_launch execution
// (zero-init at load; restored by k_dst / k_tail_alpha at the end of each run)
__device__ float  g_xlS[Nv * 64];
__device__ float  g_aS[Nv];
__device__ float  g_aD[Nv];
__device__ int    g_bcnt[Nv + 2];     // [Nv] reused as float sum(ea)
__device__ float2 g_bsv[Nv * CAP];    // packed (src-as-float-bits, ea)
__device__ int    g_bedge[Nv * CAP];
__device__ float  g_alphaC[Nv * CAP]; // unnormalized p, CSR-slot order
__device__ float  g_alphaP[Ev];       // normalized alpha per unique edge
__device__ float  g_selfNorm[Nv];
__device__ uint4  g_Wimg[1152];       // 18432B: W_hi [64][72]bf16 | W_lo

// ---------------- helpers ----------------
__device__ __forceinline__ uint32_t smem_to_u32(const void* p) {
    uint32_t a;
    asm("{ .reg .u64 t; cvta.to.shared.u64 t, %1; cvt.u32.u64 %0, t; }" : "=r"(a) : "l"(p));
    return a;
}
__device__ __forceinline__ uint32_t pack_hi(float2 v) {
    __nv_bfloat162 h = __float22bfloat162_rn(v);
    return *(uint32_t*)&h;
}
__device__ __forceinline__ uint32_t pack_lo(float2 v, uint32_t hi) {
    __nv_bfloat162 h = *(__nv_bfloat162*)&hi;
    float2 hf = __bfloat1622float2(h);
    float2 r; r.x = v.x - hf.x; r.y = v.y - hf.y;
    __nv_bfloat162 l = __float22bfloat162_rn(r);
    return *(uint32_t*)&l;
}
#define LDMX2(r, a) \
    asm volatile("ldmatrix.sync.aligned.m8n8.x2.shared.b16 {%0,%1}, [%2];" \
        : "=r"((r)[0]), "=r"((r)[1]) : "r"(a))
#define MMA16816(c, a, b) \
    asm volatile("mma.sync.aligned.m16n8k16.row.col.f32.bf16.bf16.f32 " \
        "{%0,%1,%2,%3}, {%4,%5,%6,%7}, {%8,%9}, {%0,%1,%2,%3};" \
        : "+f"((c)[0]), "+f"((c)[1]), "+f"((c)[2]), "+f"((c)[3]) \
        : "r"((a)[0]), "r"((a)[1]), "r"((a)[2]), "r"((a)[3]), "r"((b)[0]), "r"((b)[1]))

// ---------------- W -> bf16 hi/lo image [64 rows][72 bf16] ----------------
__global__ void k_wconv(const float* __restrict__ W) {
    int p = blockIdx.x * 256 + threadIdx.x;          // 8 blocks x 256 = 2048
    char* img = (char*)g_Wimg;
    int c = p >> 5, cp = p & 31;
    float2 v = *(const float2*)(W + c * 64 + cp * 2);
    uint32_t hu = pack_hi(v);
    uint32_t lu = pack_lo(v, hu);
    *(unsigned*)(img + c * 144 + cp * 4) = hu;
    *(unsigned*)(img + 9216 + c * 144 + cp * 4) = lu;
}

// ---- REST gemm: M=128 tile (rows 5120..79999), stages from g_Wimg ----
__global__ void __launch_bounds__(256, 2) k_gemm128(const float* __restrict__ x,
                                                    const float* __restrict__ bias,
                                                    float* __restrict__ out,
                                                    int blockOff) {
    __shared__ char smB[18432];
    int tid = threadIdx.x, wid = tid >> 5, lane = tid & 31;
    int nb = (blockIdx.x + blockOff) * 128;

    {
        uint4* dst = (uint4*)smB;
#pragma unroll
        for (int i = 0; i < 5; i++) {
            int j = tid + i * 256;
            if (j < 1152) dst[j] = g_Wimg[j];
        }
    }

    int r0 = wid * 16 + (lane >> 2);
    const float* xr = x + (size_t)(nb + r0) * 64 + (lane & 3) * 2;
    float2 v[4][4];
#pragma unroll
    for (int kc = 0; kc < 4; kc++) {
        v[kc][0] = *(const float2*)(xr + kc * 16);
        v[kc][1] = *(const float2*)(xr + 8 * 64 + kc * 16);
        v[kc][2] = *(const float2*)(xr + kc * 16 + 8);
        v[kc][3] = *(const float2*)(xr + 8 * 64 + kc * 16 + 8);
    }
    uint32_t ahi[4][4], alo[4][4];
#pragma unroll
    for (int kc = 0; kc < 4; kc++)
#pragma unroll
        for (int j = 0; j < 4; j++) {
            ahi[kc][j] = pack_hi(v[kc][j]);
            alo[kc][j] = pack_lo(v[kc][j], ahi[kc][j]);
        }
    __syncthreads();

    uint32_t sb = smem_to_u32(smB);
    uint32_t bOff = (lane & 7) * 144 + ((lane >> 3) & 1) * 16;

    float acc[8][4];
#pragma unroll
    for (int nt = 0; nt < 8; nt++)
#pragma unroll
        for (int j = 0; j < 4; j++) acc[nt][j] = 0.f;

#pragma unroll
    for (int kc = 0; kc < 4; kc++) {
        uint32_t bh[8][2], bl[8][2];
#pragma unroll
        for (int nt = 0; nt < 8; nt++) {
            uint32_t ba = sb + nt * 1152 + bOff + kc * 32;
            LDMX2(bh[nt], ba);
            LDMX2(bl[nt], ba + 9216);
        }
#pragma unroll
        for (int nt = 0; nt < 8; nt++) {
            MMA16816(acc[nt], ahi[kc], bh[nt]);
            MMA16816(acc[nt], ahi[kc], bl[nt]);
            MMA16816(acc[nt], alo[kc], bh[nt]);
        }
    }

    int n0 = nb + r0, n1 = n0 + 8;
#pragma unroll
    for (int nt = 0; nt < 8; nt++) {
        int col = nt * 8 + (lane & 3) * 2;
        float2 bb2 = *(const float2*)(bias + col);
        float2 o0, o1;
        o0.x = acc[nt][0] + bb2.x; o0.y = acc[nt][1] + bb2.y;
        o1.x = acc[nt][2] + bb2.x; o1.y = acc[nt][3] + bb2.y;
        *(float2*)(out + (size_t)n0 * 64 + col) = o0;
        *(float2*)(out + (size_t)n1 * 64 + col) = o1;
    }
}

// ---- HEAD gemm: M=64 tile (rows 0..5119), inline W conversion, attn epilogue ----
__global__ void __launch_bounds__(256, 2) k_gemm64(const float* __restrict__ x,
                                                   const float* __restrict__ W,
                                                   const float* __restrict__ bias,
                                                   const float* __restrict__ attS,
                                                   const float* __restrict__ attD,
                                                   float* __restrict__ out) {
    __shared__ char smB[18432];
    __shared__ float PS[64], PD[64];
    int tid = threadIdx.x, wid = tid >> 5, lane = tid & 31;
    int nb = blockIdx.x * 64;

    // inline W -> bf16 hi/lo conversion (head only; no wconv dependency)
#pragma unroll
    for (int it = 0; it < 8; it++) {
        int i = tid + it * 256;
        int c = i >> 5, cp = i & 31;
        float2 wv = *(const float2*)(W + c * 64 + cp * 2);
        uint32_t hu = pack_hi(wv);
        uint32_t lu = pack_lo(wv, hu);
        *(uint32_t*)(smB + c * 144 + cp * 4) = hu;
        *(uint32_t*)(smB + 9216 + c * 144 + cp * 4) = lu;
    }

    int rg = (wid & 3) * 16;          // row group within 64-row tile
    int cg = (wid >> 2) * 32;         // column half: 0 or 32
    int rloc = rg + (lane >> 2);
    int r0g = nb + rloc;
    const float* xr = x + (size_t)r0g * 64 + (lane & 3) * 2;
    float2 v[4][4];
#pragma unroll
    for (int kc = 0; kc < 4; kc++) {
        v[kc][0] = *(const float2*)(xr + kc * 16);
        v[kc][1] = *(const float2*)(xr + 8 * 64 + kc * 16);
        v[kc][2] = *(const float2*)(xr + kc * 16 + 8);
        v[kc][3] = *(const float2*)(xr + 8 * 64 + kc * 16 + 8);
    }
    uint32_t ahi[4][4], alo[4][4];
#pragma unroll
    for (int kc = 0; kc < 4; kc++)
#pragma unroll
        for (int j = 0; j < 4; j++) {
            ahi[kc][j] = pack_hi(v[kc][j]);
            alo[kc][j] = pack_lo(v[kc][j], ahi[kc][j]);
        }
    __syncthreads();

    uint32_t sb = smem_to_u32(smB);
    uint32_t bOff = (lane & 7) * 144 + ((lane >> 3) & 1) * 16;
    int ntBase = cg >> 3;             // 0 or 4

    float acc[4][4];
#pragma unroll
    for (int nt = 0; nt < 4; nt++)
#pragma unroll
        for (int j = 0; j < 4; j++) acc[nt][j] = 0.f;

#pragma unroll
    for (int kc = 0; kc < 4; kc++) {
        uint32_t bh[4][2], bl[4][2];
#pragma unroll
        for (int nt = 0; nt < 4; nt++) {
            uint32_t ba = sb + (ntBase + nt) * 1152 + bOff + kc * 32;
            LDMX2(bh[nt], ba);
            LDMX2(bl[nt], ba + 9216);
        }
#pragma unroll
        for (int nt = 0; nt < 4; nt++) {
            MMA16816(acc[nt], ahi[kc], bh[nt]);
            MMA16816(acc[nt], ahi[kc], bl[nt]);
            MMA16816(acc[nt], alo[kc], bh[nt]);
        }
    }

    int n0 = nb + rloc, n1 = n0 + 8;
#pragma unroll
    for (int nt = 0; nt < 4; nt++) {
        int col = cg + nt * 8 + (lane & 3) * 2;
        float2 bb2 = *(const float2*)(bias + col);
        float2 o0, o1;
        o0.x = acc[nt][0] + bb2.x; o0.y = acc[nt][1] + bb2.y;
        o1.x = acc[nt][2] + bb2.x; o1.y = acc[nt][3] + bb2.y;
        *(float2*)(out + (size_t)n0 * 64 + col) = o0;
        *(float2*)(out + (size_t)n1 * 64 + col) = o1;
        if (n0 < Nv) {
            float2 s0; s0.x = acc[nt][0]; s0.y = acc[nt][1];
            *(float2*)(g_xlS + n0 * 64 + col) = s0;
        }
        if (n1 < Nv) {
            float2 s1; s1.x = acc[nt][2]; s1.y = acc[nt][3];
            *(float2*)(g_xlS + n1 * 64 + col) = s1;
        }
    }
    float ps0 = 0.f, pd0 = 0.f, ps1 = 0.f, pd1 = 0.f;
#pragma unroll
    for (int nt = 0; nt < 4; nt++) {
        int col = cg + nt * 8 + (lane & 3) * 2;
        float2 a2 = *(const float2*)(attS + col);
        float2 d2 = *(const float2*)(attD + col);
        ps0 += acc[nt][0] * a2.x + acc[nt][1] * a2.y;
        pd0 += acc[nt][0] * d2.x + acc[nt][1] * d2.y;
        ps1 += acc[nt][2] * a2.x + acc[nt][3] * a2.y;
        pd1 += acc[nt][2] * d2.x + acc[nt][3] * d2.y;
    }
#pragma unroll
    for (int o = 1; o <= 2; o <<= 1) {
        ps0 += __shfl_xor_sync(0xffffffffu, ps0, o);
        pd0 += __shfl_xor_sync(0xffffffffu, pd0, o);
        ps1 += __shfl_xor_sync(0xffffffffu, ps1, o);
        pd1 += __shfl_xor_sync(0xffffffffu, pd1, o);
    }
    if (cg == 32 && (lane & 3) == 0) {
        PS[rloc] = ps0; PD[rloc] = pd0;
        PS[rloc + 8] = ps1; PD[rloc + 8] = pd1;
    }
    __syncthreads();
    if (cg == 0 && (lane & 3) == 0) {
        if (n0 < Nv) { g_aS[n0] = ps0 + PS[rloc];     g_aD[n0] = pd0 + PD[rloc]; }
        if (n1 < Nv) { g_aS[n1] = ps1 + PS[rloc + 8]; g_aD[n1] = pd1 + PD[rloc + 8]; }
    }
}

// ------- bucket scatter + ea sum (counters pre-zeroed by invariant) -------
__global__ void k_scatter(const int* __restrict__ ei, const float* __restrict__ ea) {
    int e = blockIdx.x * 256 + threadIdx.x;
    int d = ei[Ev + e];
    int s = ei[e];
    float v = ea[e];
    int pos = atomicAdd(&g_bcnt[d], 1);
    int idx = d * CAP + pos;
    float2 sv; sv.x = __int_as_float(s); sv.y = v;
    g_bsv[idx] = sv;
    g_bedge[idx] = e;
    float t = v;
#pragma unroll
    for (int o = 16; o; o >>= 1) t += __shfl_xor_sync(0xffffffffu, t, o);
    __shared__ float sh[8];
    if ((threadIdx.x & 31) == 0) sh[threadIdx.x >> 5] = t;
    __syncthreads();
    if (threadIdx.x < 8) {
        float w = sh[threadIdx.x];
#pragma unroll
        for (int o = 4; o; o >>= 1) w += __shfl_xor_sync(0xffu, w, o);
        if (threadIdx.x == 0) atomicAdd((float*)g_bcnt + Nv, w);
    }
}

// ------- per-destination softmax + aggregation: one warp per dst -------
// Also restores g_bcnt[d] = 0 for the next graph execution.
__global__ void __launch_bounds__(256) k_dst(const float* __restrict__ W_edge,
                                             const float* __restrict__ attE,
                                             const float* __restrict__ bias,
                                             float* __restrict__ out) {
    int wIdx = threadIdx.x >> 5;
    int d = blockIdx.x * 8 + wIdx;
    int lane = threadIdx.x & 31;
    float cv = W_edge[lane] * attE[lane] + W_edge[lane + 32] * attE[lane + 32];
#pragma unroll
    for (int o = 16; o; o >>= 1) cv += __shfl_xor_sync(0xffffffffu, cv, o);
    float meanC = ((const float*)g_bcnt)[Nv] * (1.f / (float)Ev) * cv;

    int cnt = g_bcnt[d];
    int base = d * CAP;
    float aDd = g_aD[d];
    float pSelf;
    {
        float xv = g_aS[d] + aDd + meanC;
        xv = xv > 0.f ? xv : 0.2f * xv;
        pSelf = __expf(xv);
    }
    __shared__ float sP[8][32];
    __shared__ int   sS[8][32];
    float a0x = 0.f, a0y = 0.f, a1x = 0.f, a1y = 0.f;
    float a2x = 0.f, a2y = 0.f, a3x = 0.f, a3y = 0.f;
    float psum = 0.f;
    for (int b0 = 0; b0 < cnt; b0 += 32) {
        int m = cnt - b0; if (m > 32) m = 32;
        if (lane < m) {
            int idx = base + b0 + lane;
            float2 sv = g_bsv[idx];
            int s = __float_as_int(sv.x);
            float xv = g_aS[s] + aDd + sv.y * cv;
            xv = xv > 0.f ? xv : 0.2f * xv;
            float p = __expf(xv);
            psum += p;
            sP[wIdx][lane] = p;
            sS[wIdx][lane] = s;
            g_alphaC[idx] = p;
        }
        __syncwarp();
        int j = 0;
        for (; j + 4 <= m; j += 4) {
            float p0 = sP[wIdx][j],     p1 = sP[wIdx][j + 1];
            float p2 = sP[wIdx][j + 2], p3 = sP[wIdx][j + 3];
            int   q0 = sS[wIdx][j],     q1 = sS[wIdx][j + 1];
            int   q2 = sS[wIdx][j + 2], q3 = sS[wIdx][j + 3];
            float2 v0 = *(const float2*)(g_xlS + q0 * 64 + lane * 2);
            float2 v1 = *(const float2*)(g_xlS + q1 * 64 + lane * 2);
            float2 v2 = *(const float2*)(g_xlS + q2 * 64 + lane * 2);
            float2 v3 = *(const float2*)(g_xlS + q3 * 64 + lane * 2);
            a0x += p0 * v0.x; a0y += p0 * v0.y;
            a1x += p1 * v1.x; a1y += p1 * v1.y;
            a2x += p2 * v2.x; a2y += p2 * v2.y;
            a3x += p3 * v3.x; a3y += p3 * v3.y;
        }
        for (; j < m; j++) {
            float p0 = sP[wIdx][j];
            int   q0 = sS[wIdx][j];
            float2 v0 = *(const float2*)(g_xlS + q0 * 64 + lane * 2);
            a0x += p0 * v0.x; a0y += p0 * v0.y;
        }
        __syncwarp();
    }
    float accx = (a0x + a1x) + (a2x + a3x);
    float accy = (a0y + a1y) + (a2y + a3y);
#pragma unroll
    for (int o = 16; o; o >>= 1) psum += __shfl_xor_sync(0xffffffffu, psum, o);
    float denom = (float)Bv * psum + pSelf;
    float rd = 1.f / (denom + 1e-16f);
    float2 xs = *(const float2*)(g_xlS + d * 64 + lane * 2);
    float2 bb = *(const float2*)(bias + lane * 2);
    float2 o2;
    o2.x = ((float)Bv * accx + pSelf * xs.x) * rd + bb.x;
    o2.y = ((float)Bv * accy + pSelf * xs.y) * rd + bb.y;
    *(float2*)(out + (long long)d * 64 + lane * 2) = o2;
    if (lane == 0) { g_selfNorm[d] = pSelf * rd; g_bcnt[d] = 0; }  // restore invariant
    for (int i = lane; i < cnt; i += 32) {
        int idx = base + i;
        g_alphaP[g_bedge[idx]] = g_alphaC[idx] * rd;
    }
}

// ------- tail float4 generators -------
__device__ __forceinline__ float4 tail_sd_val(const int* __restrict__ ei, int i) {
    float4 v;
    if (i < ETOTv) {
        if (i < BEv) {
            int e = i - (i / Ev) * Ev;
            v.x = (float)ei[e]; v.y = (float)ei[e + 1];
            v.z = (float)ei[e + 2]; v.w = (float)ei[e + 3];
        } else {
            float b0 = (float)(i - BEv);
            v.x = b0; v.y = b0 + 1.f; v.z = b0 + 2.f; v.w = b0 + 3.f;
        }
    } else {
        int k = i - ETOTv;
        if (k < BEv) {
            int e = k - (k / Ev) * Ev;
            v.x = (float)ei[Ev + e]; v.y = (float)ei[Ev + e + 1];
            v.z = (float)ei[Ev + e + 2]; v.w = (float)ei[Ev + e + 3];
        } else {
            float b0 = (float)(k - BEv);
            v.x = b0; v.y = b0 + 1.f; v.z = b0 + 2.f; v.w = b0 + 3.f;
        }
    }
    return v;
}

__global__ void k_tail_sd(const int* __restrict__ ei, float* __restrict__ outTail) {
    int base4 = blockIdx.x * 1024 + threadIdx.x;
    float4 v[4];
    int idx[4];
#pragma unroll
    for (int k = 0; k < 4; k++) {
        idx[k] = base4 + k * 256;
        int i = idx[k] * 4;
        if (i < 2 * ETOTv) v[k] = tail_sd_val(ei, i);
    }
#pragma unroll
    for (int k = 0; k < 4; k++) {
        int i = idx[k] * 4;
        if (i < 2 * ETOTv) *(float4*)(outTail + i) = v[k];
    }
}

__device__ __forceinline__ float4 tail_alpha_val(int i) {
    float4 v;
    if (i < BEv) {
        int e = i - (i / Ev) * Ev;
        v = *(const float4*)(g_alphaP + e);
    } else {
        int d = i - BEv;
        if (d + 3 < Nv) {
            v.x = g_selfNorm[d]; v.y = g_selfNorm[d + 1];
            v.z = g_selfNorm[d + 2]; v.w = g_selfNorm[d + 3];
        } else {
            v.x = (d     < Nv) ? g_selfNorm[d]     : 1.0f;
            v.y = (d + 1 < Nv) ? g_selfNorm[d + 1] : 1.0f;
            v.z = (d + 2 < Nv) ? g_selfNorm[d + 2] : 1.0f;
            v.w = (d + 3 < Nv) ? g_selfNorm[d + 3] : 1.0f;
        }
    }
    return v;
}

__global__ void k_tail_alpha(float* __restrict__ outA, int totalA) {
    // restore invariant: zero the ea-sum accumulator (runs after k_dst on same stream)
    if (blockIdx.x == 0 && threadIdx.x == 0) ((float*)g_bcnt)[Nv] = 0.f;
    int base4 = blockIdx.x * 1024 + threadIdx.x;
    float4 v[4];
    int idx[4];
#pragma unroll
    for (int k = 0; k < 4; k++) {
        idx[k] = base4 + k * 256;
        int i = idx[k] * 4;
        if (i < totalA) v[k] = tail_alpha_val(i);
    }
#pragma unroll
    for (int k = 0; k < 4; k++) {
        int i = idx[k] * 4;
        if (i < totalA) *(float4*)(outA + i) = v[k];
    }
}

__global__ void k_zero_sum() {
    ((float*)g_bcnt)[Nv] = 0.f;
}

// ---------------- launch ----------------
extern "C" void kernel_launch(void* const* d_in, const int* in_sizes, int n_in,
                              void* d_out, int out_size) {
    const float* data   = (const float*)d_in[0];
    const int*   ei     = (const int*)  d_in[1];
    const float* ea     = (const float*)d_in[2];
    const float* W      = (const float*)d_in[3];
    const float* W_edge = (const float*)d_in[4];
    const float* attS   = (const float*)d_in[5];
    const float* attD   = (const float*)d_in[6];
    const float* attE   = (const float*)d_in[7];
    const float* bias   = (const float*)d_in[8];
    float* out = (float*)d_out;

    static cudaStream_t sB = nullptr, sC = nullptr, sD = nullptr;
    static cudaEvent_t eFork = nullptr, eB = nullptr, eC = nullptr, eD = nullptr;
    if (!sB) {
        int prLo = 0, prHi = 0;
        cudaDeviceGetStreamPriorityRange(&prLo, &prHi);
        cudaStreamCreateWithFlags(&sB, cudaStreamNonBlocking);
        cudaStreamCreateWithFlags(&sC, cudaStreamNonBlocking);
        cudaStreamCreateWithPriority(&sD, cudaStreamNonBlocking, prLo); // bulk gemm lowest prio
        cudaEventCreateWithFlags(&eFork, cudaEventDisableTiming);
        cudaEventCreateWithFlags(&eB, cudaEventDisableTiming);
        cudaEventCreateWithFlags(&eC, cudaEventDisableTiming);
        cudaEventCreateWithFlags(&eD, cudaEventDisableTiming);
    }

    cudaEventRecord(eFork, 0);
    cudaStreamWaitEvent(sB, eFork, 0);
    cudaStreamWaitEvent(sC, eFork, 0);
    cudaStreamWaitEvent(sD, eFork, 0);

    // HEAD gemm immediately on main (critical path, no wconv dependency)
    k_gemm64<<<80, 256>>>(data, W, bias, attS, attD, out);

    // side streams, all start at the fork
    k_scatter<<<NPART, 256, 0, sB>>>(ei, ea);          // counters pre-zeroed by invariant
    cudaEventRecord(eB, sB);

    if (out_size > OUT_MAIN) {
        int nblk = (2 * ETOTv / 4 + 1023) / 1024;
        k_tail_sd<<<nblk, 256, 0, sC>>>(ei, out + OUT_MAIN);
    }
    cudaEventRecord(eC, sC);

    k_wconv<<<8, 256, 0, sD>>>(W);
    k_gemm128<<<BNv / 128 - HEADBLKS, 256, 0, sD>>>(data, bias, out, HEADBLKS);
    cudaEventRecord(eD, sD);

    // main: wait CSR, then softmax/aggregate (overlaps gemm_rest), alpha tail
    cudaStreamWaitEvent(0, eB, 0);
    k_dst<<<Nv / 8, 256>>>(W_edge, attE, bias, out);

    if (out_size > OUT_MAIN) {
        int totalA = out_size - OUT_MAIN - 2 * ETOTv;
        if (totalA > 0) {
            int nblk = ((totalA + 3) / 4 + 1023) / 1024;
            k_tail_alpha<<<nblk, 256>>>(out + OUT_MAIN + 2 * ETOTv, totalA);
        }
    } else {
        k_zero_sum<<<1, 1>>>();   // keep the ea-sum invariant in the no-tail path
    }

    cudaStreamWaitEvent(0, eC, 0);
    cudaStreamWaitEvent(0, eD, 0);
}